// round 5
// baseline (speedup 1.0000x reference)
#include <cuda_runtime.h>
#include <math.h>
#include <stdint.h>

// ---------------- problem constants ----------------
#define DIN   32
#define H1    32
#define H2    64
#define DE    16
#define NATOM 50000
#define NEDGE 100000
#define NB    50
#define NPG   1000
#define MAMN  50
#define AAFD  95
#define GDIM  128
#define KST   3
#define TLAY  6
#define EAED  98
#define FAA   160
#define N3CAT 2688      // 384 init (K*G) + 2304 root (T*K*G)
#define CC    272       // cols per o-chunk: 17 d-slices (16 + b_e) x 16 o
#define NT    128       // nodes per fused-conv block

// ---------------- device scratch ----------------
__device__ float g_h1[NATOM * H1];
__device__ float g_h2[NATOM * H2];
__device__ float g_haa[NB * MAMN * FAA];
__device__ float g_C3[NB * MAMN * N3CAT];
__device__ float g_ao[NB * KST * MAMN * GDIM];
__device__ float g_W1n[DIN * (2 * CC)];
__device__ float g_W2n[H1 * (4 * CC)];
__device__ float g_W3cat[FAA * N3CAT];
__device__ int   g_cnt[NATOM];
__device__ int   g_noff[NATOM + 1];
__device__ int   g_ncur[NATOM];
__device__ int   g_eord[NEDGE];
__device__ int   g_off[MAMN + 1];
__device__ int   g_csrc[EAED];
__device__ float g_cnorm[EAED];

// ---------------- f32x2 helpers ----------------
__device__ __forceinline__ unsigned long long pk2(float x) {
    unsigned long long r; unsigned u = __float_as_uint(x);
    asm("mov.b64 %0, {%1, %1};" : "=l"(r) : "r"(u));
    return r;
}
__device__ __forceinline__ float2 unpk2(unsigned long long v) {
    unsigned lo, hi;
    asm("mov.b64 {%0, %1}, %2;" : "=r"(lo), "=r"(hi) : "l"(v));
    return make_float2(__uint_as_float(lo), __uint_as_float(hi));
}
#define FMA2(acc, a, b) \
    asm("fma.rn.f32x2 %0, %1, %2, %3;" : "=l"(acc) : "l"(a), "l"(b), "l"(acc))

// ---------------- weight repack ----------------
// conv layout: Wn[f][ch*CC + d*16 + o16], o = ch*16+o16; d==16 slice = b_e.
__global__ void prep_weights(const float* __restrict__ We1, const float* __restrict__ be1,
                             const float* __restrict__ We2, const float* __restrict__ be2,
                             const float* __restrict__ ainit, const float* __restrict__ aroot) {
    int idx0 = blockIdx.x * blockDim.x + threadIdx.x;
    int stride = gridDim.x * blockDim.x;
    for (int idx = idx0; idx < DIN * 2 * CC; idx += stride) {
        int f = idx / (2 * CC), c = idx % (2 * CC);
        int ch = c / CC, r = c % CC, d = r >> 4, o = ch * 16 + (r & 15);
        g_W1n[idx] = (d < 16) ? We1[d * (DIN * H1) + f * H1 + o] : be1[f * H1 + o];
    }
    for (int idx = idx0; idx < H1 * 4 * CC; idx += stride) {
        int f = idx / (4 * CC), c = idx % (4 * CC);
        int ch = c / CC, r = c % CC, d = r >> 4, o = ch * 16 + (r & 15);
        g_W2n[idx] = (d < 16) ? We2[d * (H1 * H2) + f * H2 + o] : be2[f * H2 + o];
    }
    for (int idx = idx0; idx < FAA * N3CAT; idx += stride) {
        int f = idx / N3CAT, c = idx % N3CAT;
        float v = 0.f;
        if (f < 159) {
            if (c < 384) { int k = c >> 7, g = c & 127; v = ainit[(k * 159 + f) * 128 + g]; }
            else {
                int j = c - 384; int t = j / 384; int r = j - t * 384;
                int k = r >> 7, g = r & 127;
                v = aroot[((t * 3 + k) * 159 + f) * 128 + g];
            }
        }
        g_W3cat[idx] = v;
    }
}

// ---------------- CSR-by-src build ----------------
__global__ void zero_cnt_kernel() {
    int i = blockIdx.x * blockDim.x + threadIdx.x;
    if (i < NATOM) g_cnt[i] = 0;
}
__global__ void hist_kernel(const int* __restrict__ ei) {
    int e = blockIdx.x * blockDim.x + threadIdx.x;
    if (e < NEDGE) atomicAdd(&g_cnt[ei[e]], 1);
}
__global__ void scan_kernel() {
    __shared__ int sh_carry;
    __shared__ int wsum[32];
    int tid = threadIdx.x, lane = tid & 31, wid = tid >> 5;
    if (tid == 0) sh_carry = 0;
    __syncthreads();
    for (int base = 0; base < NATOM; base += 1024) {
        int i = base + tid;
        int v = (i < NATOM) ? g_cnt[i] : 0;
        int x = v;
#pragma unroll
        for (int s = 1; s < 32; s <<= 1) {
            int y = __shfl_up_sync(0xffffffffu, x, s);
            if (lane >= s) x += y;
        }
        if (lane == 31) wsum[wid] = x;
        __syncthreads();
        if (wid == 0) {
            int w = wsum[lane];
#pragma unroll
            for (int s = 1; s < 32; s <<= 1) {
                int y = __shfl_up_sync(0xffffffffu, w, s);
                if (lane >= s) w += y;
            }
            wsum[lane] = w;
        }
        __syncthreads();
        int excl = x - v + (wid > 0 ? wsum[wid - 1] : 0) + sh_carry;
        if (i < NATOM) { g_noff[i] = excl; g_ncur[i] = excl; }
        int btot = wsum[31];
        __syncthreads();
        if (tid == 0) sh_carry += btot;
        __syncthreads();
    }
    if (threadIdx.x == 0) g_noff[NATOM] = sh_carry;
}
__global__ void scatter_kernel(const int* __restrict__ ei) {
    int e = blockIdx.x * blockDim.x + threadIdx.x;
    if (e < NEDGE) {
        int slot = atomicAdd(&g_ncur[ei[e]], 1);
        g_eord[slot] = e;
    }
}

// amino graph CSR (tiny, serial)
__global__ void prep_csr(const int* __restrict__ aei) {
    if (blockIdx.x != 0 || threadIdx.x != 0) return;
    int deg[MAMN]; float dinv[MAMN]; int cur[MAMN];
    for (int m = 0; m < MAMN; m++) deg[m] = 0;
    for (int e = 0; e < EAED; e++) deg[aei[EAED + e]]++;
    for (int m = 0; m < MAMN; m++) dinv[m] = deg[m] > 0 ? 1.0f / sqrtf((float)deg[m]) : 0.0f;
    int off = 0;
    for (int m = 0; m < MAMN; m++) { g_off[m] = off; cur[m] = off; off += deg[m]; }
    g_off[MAMN] = off;
    for (int e = 0; e < EAED; e++) {
        int s = aei[e], d = aei[EAED + e];
        int slot = cur[d]++;
        g_csrc[slot] = s;
        g_cnorm[slot] = dinv[s] * dinv[d];
    }
}

// ---------------- h init: h[v,o] = bias[o] + sum_f A'[v,f] root[f,o] ----------------
template <int FIN, int FOUT, bool RELU>
__global__ void init_h_kernel(const float* __restrict__ A, const float* __restrict__ root,
                              const float* __restrict__ bias, float* __restrict__ out) {
    int idx = blockIdx.x * blockDim.x + threadIdx.x;
    if (idx >= NATOM * FOUT) return;
    int v = idx / FOUT, o = idx - v * FOUT;
    float s = bias[o];
    const float* ar = A + (size_t)v * FIN;
#pragma unroll
    for (int f = 0; f < FIN; f++) {
        float a = ar[f];
        if (RELU) a = fmaxf(a, 0.f);
        s += a * root[f * FOUT + o];
    }
    out[idx] = s;
}

// ---------------- fused conv: per-block node GEMM (smem t-tile) + edge scatter ----------------
// t[n][d*16+o16] = sum_f A'[n,f] * Wn[f][ch*CC + d*16+o16]; d==16 is the b_e slice.
// msg[e][o] = sum_{d<16} ea[e,d]*t[src][d,o] + t[src][16,o]; atomicAdd into hout[dst].
template <int FIN, int FOUT, int OCH, bool RELU>
__global__ __launch_bounds__(512, 1)
void fused_conv(const float* __restrict__ A, const float* __restrict__ Wn,
                const int* __restrict__ ei, const float* __restrict__ ea,
                float* __restrict__ hout) {
    extern __shared__ char sm[];
    float* t_s = (float*)sm;                 // NT*CC
    float* W_s = t_s + NT * CC;              // FIN*CC
    float* A_s = W_s + FIN * CC;             // NT*FIN
    int tid = threadIdx.x;
    int n0 = blockIdx.x * NT;
    // load A tile (relu fused)
    for (int i = tid; i < NT * FIN / 4; i += 512) {
        int r = i / (FIN / 4), c4 = (i % (FIN / 4)) * 4;
        int gr = n0 + r;
        float4 v = make_float4(0.f, 0.f, 0.f, 0.f);
        if (gr < NATOM) {
            v = *(const float4*)(A + (size_t)gr * FIN + c4);
            if (RELU) {
                v.x = fmaxf(v.x, 0.f); v.y = fmaxf(v.y, 0.f);
                v.z = fmaxf(v.z, 0.f); v.w = fmaxf(v.w, 0.f);
            }
        }
        *(float4*)&A_s[r * FIN + c4] = v;
    }
    int nend = n0 + NT < NATOM ? n0 + NT : NATOM;
    int estart = g_noff[n0], eend = g_noff[nend];
    int cpb = tid & 31, ng = tid >> 5;       // 16 node-groups of 8
    int wid = tid >> 5, lane = tid & 31;
    int d2 = lane >> 4, o = lane & 15;

    for (int ch = 0; ch < OCH; ch++) {
        __syncthreads();  // A_s ready / prev edge phase done (t_s reusable)
        for (int i = tid; i < FIN * (CC / 4); i += 512) {
            int r = i / (CC / 4), c4 = (i % (CC / 4)) * 4;
            *(float4*)&W_s[r * CC + c4] =
                *(const float4*)(Wn + (size_t)r * (OCH * CC) + ch * CC + c4);
        }
        __syncthreads();
        // GEMM: thread owns 8 nodes x up-to-5 col pairs
        unsigned long long acc[8][5];
#pragma unroll
        for (int r = 0; r < 8; r++)
#pragma unroll
            for (int j = 0; j < 5; j++) acc[r][j] = 0ull;
        bool has5 = (cpb < 8);  // 136 pairs = 4*32 + 8
#pragma unroll 4
        for (int k = 0; k < FIN; k++) {
            unsigned long long a2[8];
#pragma unroll
            for (int r = 0; r < 8; r++) a2[r] = pk2(A_s[(ng * 8 + r) * FIN + k]);
#pragma unroll
            for (int j = 0; j < 4; j++) {
                unsigned long long w = *(const unsigned long long*)&W_s[k * CC + (cpb + 32 * j) * 2];
#pragma unroll
                for (int r = 0; r < 8; r++) FMA2(acc[r][j], a2[r], w);
            }
            if (has5) {
                unsigned long long w = *(const unsigned long long*)&W_s[k * CC + (cpb + 128) * 2];
#pragma unroll
                for (int r = 0; r < 8; r++) FMA2(acc[r][4], a2[r], w);
            }
        }
#pragma unroll
        for (int j = 0; j < 4; j++)
#pragma unroll
            for (int r = 0; r < 8; r++)
                *(unsigned long long*)&t_s[(ng * 8 + r) * CC + (cpb + 32 * j) * 2] = acc[r][j];
        if (has5)
#pragma unroll
            for (int r = 0; r < 8; r++)
                *(unsigned long long*)&t_s[(ng * 8 + r) * CC + (cpb + 128) * 2] = acc[r][4];
        __syncthreads();
        // edge phase: warp per edge
        for (int eidx = estart + wid; eidx < eend; eidx += 16) {
            int e = g_eord[eidx];
            int src = ei[e], dst = ei[NEDGE + e];
            int sl = src - n0;
            float av = (lane < 16) ? ea[(size_t)e * 16 + lane] : 1.0f;
            float s = 0.f;
#pragma unroll
            for (int j = 0; j < 9; j++) {
                int d = 2 * j + d2;
                int dc = d < 17 ? d : 0;
                float ed = __shfl_sync(0xffffffffu, av, dc);
                if (d < 17) s += ed * t_s[sl * CC + d * 16 + o];
            }
            s += __shfl_down_sync(0xffffffffu, s, 16);
            if (lane < 16)
                atomicAdd(&hout[(size_t)dst * FOUT + ch * 16 + o], s);
        }
    }
}

// ---------------- f32x2 GEMM (gemm3): C[M,N] = A[M,K] @ B[K,N] ----------------
__global__ __launch_bounds__(256, 2)
void gemm_x2_kernel(const float* __restrict__ A, const float* __restrict__ B,
                    float* __restrict__ C, int M, int N, int K) {
    __shared__ float As[32][128];
    __shared__ float Bs[32][128];
    int bm = blockIdx.y * 128, bn = blockIdx.x * 128;
    int tid = threadIdx.x;
    int ty = tid >> 4, tx = tid & 15;
    unsigned long long acc[8][4];
#pragma unroll
    for (int i = 0; i < 8; i++)
#pragma unroll
        for (int j = 0; j < 4; j++) acc[i][j] = 0ull;
    for (int k0 = 0; k0 < K; k0 += 32) {
#pragma unroll
        for (int j = 0; j < 4; j++) {
            int f4 = tid + j * 256;
            int r = f4 >> 3, cq = (f4 & 7) * 4;
            int gr = bm + r;
            float4 v = make_float4(0.f, 0.f, 0.f, 0.f);
            if (gr < M) v = *(const float4*)(A + (size_t)gr * K + k0 + cq);
            As[cq + 0][r] = v.x; As[cq + 1][r] = v.y;
            As[cq + 2][r] = v.z; As[cq + 3][r] = v.w;
        }
#pragma unroll
        for (int j = 0; j < 4; j++) {
            int f4 = tid + j * 256;
            int r = f4 >> 5, c4 = (f4 & 31) * 4;
            int gc = bn + c4;
            float4 v = make_float4(0.f, 0.f, 0.f, 0.f);
            if (gc < N) v = *(const float4*)(B + (size_t)(k0 + r) * N + gc);
            *(float4*)&Bs[r][c4] = v;
        }
        __syncthreads();
#pragma unroll
        for (int kk = 0; kk < 32; kk++) {
            float4 av0 = *(const float4*)&As[kk][ty * 8];
            float4 av1 = *(const float4*)&As[kk][ty * 8 + 4];
            ulonglong2 bv0 = *(const ulonglong2*)&Bs[kk][tx * 8];
            ulonglong2 bv1 = *(const ulonglong2*)&Bs[kk][tx * 8 + 4];
            unsigned long long a2[8];
            a2[0] = pk2(av0.x); a2[1] = pk2(av0.y); a2[2] = pk2(av0.z); a2[3] = pk2(av0.w);
            a2[4] = pk2(av1.x); a2[5] = pk2(av1.y); a2[6] = pk2(av1.z); a2[7] = pk2(av1.w);
            unsigned long long bb[4] = {bv0.x, bv0.y, bv1.x, bv1.y};
#pragma unroll
            for (int i = 0; i < 8; i++) {
                FMA2(acc[i][0], a2[i], bb[0]);
                FMA2(acc[i][1], a2[i], bb[1]);
                FMA2(acc[i][2], a2[i], bb[2]);
                FMA2(acc[i][3], a2[i], bb[3]);
            }
        }
        __syncthreads();
    }
#pragma unroll
    for (int i = 0; i < 8; i++) {
        int gr = bm + ty * 8 + i;
        if (gr >= M) continue;
#pragma unroll
        for (int h = 0; h < 2; h++) {
            int c0 = bn + tx * 8 + h * 4;
            if (c0 < N) {
                float2 p0 = unpk2(acc[i][2 * h]);
                float2 p1 = unpk2(acc[i][2 * h + 1]);
                float4 v = make_float4(p0.x, p0.y, p1.x, p1.y);
                *(float4*)(C + (size_t)gr * N + c0) = v;
            }
        }
    }
}

// ---------------- attention readout (relu(h2) fused in) ----------------
__global__ void readout_kernel(const float* __restrict__ aaf, const int* __restrict__ labels,
                               const float* __restrict__ Wa, const float* __restrict__ ba) {
    __shared__ float lg[NPG];
    __shared__ float aas[MAMN * H2];
    __shared__ float red[256];
    __shared__ float was[H2];
    int b = blockIdx.x, tid = threadIdx.x;
    const float* Hrow = g_h2 + (size_t)b * NPG * H2;
    if (tid < H2) was[tid] = Wa[tid];
    __syncthreads();
    float lmax = -1e30f;
    for (int i = tid; i < NPG; i += 256) {
        float s = ba[0];
        const float* hr = Hrow + (size_t)i * H2;
        for (int o = 0; o < H2; o++) s += fmaxf(hr[o], 0.f) * was[o];
        lg[i] = s;
        lmax = fmaxf(lmax, s);
    }
    red[tid] = lmax; __syncthreads();
    for (int s = 128; s > 0; s >>= 1) { if (tid < s) red[tid] = fmaxf(red[tid], red[tid + s]); __syncthreads(); }
    float mx = red[0]; __syncthreads();
    float lsum = 0.f;
    for (int i = tid; i < NPG; i += 256) { float e = expf(lg[i] - mx); lg[i] = e; lsum += e; }
    red[tid] = lsum; __syncthreads();
    for (int s = 128; s > 0; s >>= 1) { if (tid < s) red[tid] += red[tid + s]; __syncthreads(); }
    float inv = 1.f / red[0];
    for (int i = tid; i < MAMN * H2; i += 256) aas[i] = 0.f;
    __syncthreads();
    int warp = tid >> 5, lane = tid & 31;
    for (int i = warp; i < NPG; i += 8) {
        float w = lg[i] * inv;
        int m = labels[b * NPG + i];
        const float* hr = Hrow + (size_t)i * H2;
        atomicAdd(&aas[m * H2 + lane], w * fmaxf(hr[lane], 0.f));
        atomicAdd(&aas[m * H2 + 32 + lane], w * fmaxf(hr[32 + lane], 0.f));
    }
    __syncthreads();
    for (int idx = tid; idx < MAMN * FAA; idx += 256) {
        int m = idx / FAA, c = idx % FAA;
        float v;
        if (c < H2)       v = aas[m * H2 + c];
        else if (c < 159) v = aaf[((size_t)b * MAMN + m) * AAFD + (c - H2)];
        else              v = 0.f;
        g_haa[((size_t)b * MAMN + m) * FAA + c] = v;
    }
}

// ---------------- ARMA: one block per (graph, stack); 512 threads ----------------
__global__ __launch_bounds__(512)
void arma_kernel(const float* __restrict__ arma_w, const float* __restrict__ arma_bias) {
    __shared__ float buf[MAMN * GDIM];
    __shared__ float Ws[16 * GDIM];
    __shared__ int   s_off[MAMN + 1];
    __shared__ int   s_src[EAED];
    __shared__ float s_norm[EAED];
    int b = blockIdx.x / KST, k = blockIdx.x % KST;
    int tid = threadIdx.x;
    int g = tid & 127, mh = tid >> 7;
    if (tid < MAMN + 1) s_off[tid] = g_off[tid];
    if (tid < EAED) { s_src[tid] = g_csrc[tid]; s_norm[tid] = g_cnorm[tid]; }
    const float* Cb = g_C3 + (size_t)(b * MAMN) * N3CAT;
#pragma unroll
    for (int r = 0; r < 13; r++) {
        int m = mh + 4 * r;
        if (m < MAMN) buf[m * GDIM + g] = Cb[(size_t)m * N3CAT + k * GDIM + g];
    }
    __syncthreads();
    for (int t = 0; t < TLAY; t++) {
        if (t > 0) {
            const float* Wg = arma_w + (size_t)((t - 1) * KST + k) * GDIM * GDIM;
            float acc[13];
#pragma unroll
            for (int r = 0; r < 13; r++) acc[r] = 0.f;
            for (int p0 = 0; p0 < GDIM; p0 += 16) {
                for (int j = tid; j < 16 * GDIM; j += 512) Ws[j] = Wg[(size_t)p0 * GDIM + j];
                __syncthreads();
#pragma unroll
                for (int pp = 0; pp < 16; pp++) {
                    float w = Ws[pp * GDIM + g];
#pragma unroll
                    for (int r = 0; r < 13; r++) {
                        int m = mh + 4 * r;
                        if (m < MAMN) acc[r] += buf[m * GDIM + (p0 + pp)] * w;
                    }
                }
                __syncthreads();
            }
#pragma unroll
            for (int r = 0; r < 13; r++) {
                int m = mh + 4 * r;
                if (m < MAMN) buf[m * GDIM + g] = acc[r];
            }
            __syncthreads();
        }
        float nv[13];
        float bias = arma_bias[(t * KST + k) * GDIM + g];
#pragma unroll
        for (int r = 0; r < 13; r++) {
            int m = mh + 4 * r;
            if (m < MAMN) {
                float s = 0.f;
                for (int j = s_off[m]; j < s_off[m + 1]; j++)
                    s += s_norm[j] * buf[s_src[j] * GDIM + g];
                float v = s + Cb[(size_t)m * N3CAT + 384 + (t * KST + k) * GDIM + g] + bias;
                nv[r] = fmaxf(v, 0.f);
            }
        }
        __syncthreads();
#pragma unroll
        for (int r = 0; r < 13; r++) {
            int m = mh + 4 * r;
            if (m < MAMN) buf[m * GDIM + g] = nv[r];
        }
        __syncthreads();
    }
#pragma unroll
    for (int r = 0; r < 13; r++) {
        int m = mh + 4 * r;
        if (m < MAMN)
            g_ao[((size_t)(b * KST + k) * MAMN + m) * GDIM + g] = buf[m * GDIM + g];
    }
}

// ---------------- final head ----------------
__global__ void final_kernel(const float* __restrict__ Waa, const float* __restrict__ baa,
                             const float* __restrict__ W1, const float* __restrict__ b1,
                             const float* __restrict__ W2, const float* __restrict__ b2,
                             const float* __restrict__ W3, const float* __restrict__ b3,
                             const float* __restrict__ W4, const float* __restrict__ b4,
                             float* __restrict__ out) {
    __shared__ float gs[MAMN * 132];
    __shared__ float at[MAMN];
    __shared__ float ps[128], p1[64], p2[32], p3[16];
    int b = blockIdx.x, tid = threadIdx.x; // 128 threads
    const float* A = g_ao + (size_t)b * KST * MAMN * GDIM;
    for (int idx = tid; idx < MAMN * GDIM; idx += 128) {
        int m = idx >> 7, g = idx & 127;
        float v = (A[m * GDIM + g] + A[MAMN * GDIM + m * GDIM + g] +
                   A[2 * MAMN * GDIM + m * GDIM + g]) * (1.f / 3.f);
        gs[m * 132 + g] = v;
    }
    __syncthreads();
    if (tid < MAMN) {
        float s = baa[0];
        for (int g = 0; g < GDIM; g++) s += gs[tid * 132 + g] * Waa[g];
        at[tid] = s;
    }
    __syncthreads();
    if (tid == 0) {
        float mx = -1e30f;
        for (int m = 0; m < MAMN; m++) mx = fmaxf(mx, at[m]);
        float tot = 0.f;
        for (int m = 0; m < MAMN; m++) { float e = expf(at[m] - mx); at[m] = e; tot += e; }
        float inv = 1.f / tot;
        for (int m = 0; m < MAMN; m++) at[m] *= inv;
    }
    __syncthreads();
    { float s = 0.f; for (int m = 0; m < MAMN; m++) s += at[m] * gs[m * 132 + tid]; ps[tid] = s; }
    __syncthreads();
    if (tid < 64) { float s = b1[tid]; for (int i = 0; i < 128; i++) s += ps[i] * W1[i * 64 + tid]; p1[tid] = fmaxf(s, 0.f); }
    __syncthreads();
    if (tid < 32) { float s = b2[tid]; for (int i = 0; i < 64; i++) s += p1[i] * W2[i * 32 + tid]; p2[tid] = fmaxf(s, 0.f); }
    __syncthreads();
    if (tid < 16) { float s = b3[tid]; for (int i = 0; i < 32; i++) s += p2[i] * W3[i * 16 + tid]; p3[tid] = fmaxf(s, 0.f); }
    __syncthreads();
    if (tid == 0) { float s = b4[0]; for (int i = 0; i < 16; i++) s += p3[i] * W4[i]; out[b] = s; }
}

// ---------------- launch ----------------
extern "C" void kernel_launch(void* const* d_in, const int* in_sizes, int n_in,
                              void* d_out, int out_size) {
    const float* x         = (const float*)d_in[0];
    const float* edge_attr = (const float*)d_in[1];
    const float* aaf       = (const float*)d_in[2];
    const int*   ei        = (const int*)d_in[3];
    const int*   labels    = (const int*)d_in[4];
    const int*   aei       = (const int*)d_in[5];
    const float* We1   = (const float*)d_in[6];
    const float* be1   = (const float*)d_in[7];
    const float* root1 = (const float*)d_in[8];
    const float* bias1 = (const float*)d_in[9];
    const float* We2   = (const float*)d_in[10];
    const float* be2   = (const float*)d_in[11];
    const float* root2 = (const float*)d_in[12];
    const float* bias2 = (const float*)d_in[13];
    const float* WaAtom = (const float*)d_in[14];
    const float* baAtom = (const float*)d_in[15];
    const float* armaw  = (const float*)d_in[17];
    const float* abias  = (const float*)d_in[19];
    const float* Waa    = (const float*)d_in[20];
    const float* baa    = (const float*)d_in[21];
    const float* W1 = (const float*)d_in[22];
    const float* b1 = (const float*)d_in[23];
    const float* W2 = (const float*)d_in[24];
    const float* b2 = (const float*)d_in[25];
    const float* W3 = (const float*)d_in[26];
    const float* b3 = (const float*)d_in[27];
    const float* W4 = (const float*)d_in[28];
    const float* b4 = (const float*)d_in[29];
    float* out = (float*)d_out;

    void *ph1, *ph2, *phaa, *pC3, *pW1n, *pW2n, *pW3c;
    cudaGetSymbolAddress(&ph1, g_h1);
    cudaGetSymbolAddress(&ph2, g_h2);
    cudaGetSymbolAddress(&phaa, g_haa);
    cudaGetSymbolAddress(&pC3, g_C3);
    cudaGetSymbolAddress(&pW1n, g_W1n);
    cudaGetSymbolAddress(&pW2n, g_W2n);
    cudaGetSymbolAddress(&pW3c, g_W3cat);

    const int SMEMC = (NT * CC + 32 * CC + NT * 32) * 4;  // 190464 B
    cudaFuncSetAttribute(fused_conv<DIN, H1, 2, false>,
                         cudaFuncAttributeMaxDynamicSharedMemorySize, SMEMC);
    cudaFuncSetAttribute(fused_conv<H1, H2, 4, true>,
                         cudaFuncAttributeMaxDynamicSharedMemorySize, SMEMC);

    // CSR-by-src build
    zero_cnt_kernel<<<(NATOM + 255) / 256, 256>>>();
    hist_kernel<<<(NEDGE + 255) / 256, 256>>>(ei);
    scan_kernel<<<1, 1024>>>();
    scatter_kernel<<<(NEDGE + 255) / 256, 256>>>(ei);

    prep_weights<<<256, 256>>>(We1, be1, We2, be2,
                               (const float*)d_in[16], (const float*)d_in[18]);
    prep_csr<<<1, 32>>>(aei);

    // conv1
    init_h_kernel<DIN, H1, false><<<(NATOM * H1 + 255) / 256, 256>>>(x, root1, bias1, (float*)ph1);
    fused_conv<DIN, H1, 2, false><<<(NATOM + NT - 1) / NT, 512, SMEMC>>>(
        x, (const float*)pW1n, ei, edge_attr, (float*)ph1);

    // conv2 (A = relu(h1) fused)
    init_h_kernel<H1, H2, true><<<(NATOM * H2 + 255) / 256, 256>>>((const float*)ph1, root2, bias2, (float*)ph2);
    fused_conv<H1, H2, 4, true><<<(NATOM + NT - 1) / NT, 512, SMEMC>>>(
        (const float*)ph1, (const float*)pW2n, ei, edge_attr, (float*)ph2);

    // atom -> amino readout
    readout_kernel<<<NB, 256>>>(aaf, labels, WaAtom, baAtom);

    // ARMA init + root precompute GEMM: [2500,160] @ [160,2688]
    {
        dim3 grid((N3CAT + 127) / 128, (NB * MAMN + 127) / 128);
        gemm_x2_kernel<<<grid, 256>>>((const float*)phaa, (const float*)pW3c, (float*)pC3,
                                      NB * MAMN, N3CAT, FAA);
    }

    arma_kernel<<<NB * KST, 512>>>(armaw, abias);

    final_kernel<<<NB, 128>>>(Waa, baa, W1, b1, W2, b2, W3, b3, W4, b4, out);
}

// round 6
// speedup vs baseline: 1.2330x; 1.2330x over previous
#include <cuda_runtime.h>
#include <cuda_fp16.h>
#include <math.h>
#include <stdint.h>

// ---------------- problem constants ----------------
#define DIN   32
#define H1    32
#define H2    64
#define DE    16
#define NATOM 50000
#define NEDGE 100000
#define NB    50
#define NPG   1000
#define MAMN  50
#define AAFD  95
#define GDIM  128
#define KST   3
#define TLAY  6
#define EAED  98
#define FAA   160
#define N1CAT 576       // 512 edge-W + 32 b_e1 + 32 root1
#define E1C   544       // fp16 table width conv1 (edge + b_e)
#define N2CAT 1152      // 1024 edge-W + 64 b_e2 + 64 root2
#define E2C   1088      // fp16 table width conv2
#define N3CAT 2688      // 384 init (K*G) + 2304 root (T*K*G)

// ---------------- device scratch ----------------
__device__ __half g_C1h[(size_t)NATOM * E1C];   // 54.4 MB
__device__ __half g_C2h[(size_t)NATOM * E2C];   // 108.8 MB
__device__ float g_h1[NATOM * H1];
__device__ float g_h2[NATOM * H2];
__device__ float g_haa[NB * MAMN * FAA];
__device__ float g_C3[NB * MAMN * N3CAT];
__device__ float g_ao[NB * KST * MAMN * GDIM];
__device__ float g_W1cat[DIN * N1CAT];
__device__ float g_W2cat[H1 * N2CAT];
__device__ float g_W3cat[FAA * N3CAT];
__device__ int   g_off[MAMN + 1];
__device__ int   g_csrc[EAED];
__device__ float g_cnorm[EAED];

// ---------------- f32x2 helpers ----------------
__device__ __forceinline__ unsigned long long pk2(float x) {
    unsigned long long r; unsigned u = __float_as_uint(x);
    asm("mov.b64 %0, {%1, %1};" : "=l"(r) : "r"(u));
    return r;
}
__device__ __forceinline__ float2 unpk2(unsigned long long v) {
    unsigned lo, hi;
    asm("mov.b64 {%0, %1}, %2;" : "=r"(lo), "=r"(hi) : "l"(v));
    return make_float2(__uint_as_float(lo), __uint_as_float(hi));
}
#define FMA2(acc, a, b) \
    asm("fma.rn.f32x2 %0, %1, %2, %3;" : "=l"(acc) : "l"(a), "l"(b), "l"(acc))

// ---------------- weight repack ----------------
__global__ void prep_weights(const float* __restrict__ We1, const float* __restrict__ be1,
                             const float* __restrict__ root1,
                             const float* __restrict__ We2, const float* __restrict__ be2,
                             const float* __restrict__ root2,
                             const float* __restrict__ ainit, const float* __restrict__ aroot) {
    int idx0 = blockIdx.x * blockDim.x + threadIdx.x;
    int stride = gridDim.x * blockDim.x;
    for (int idx = idx0; idx < DIN * N1CAT; idx += stride) {
        int f = idx / N1CAT, c = idx % N1CAT;
        float v;
        if (c < 512)      { int d = c >> 5, o = c & 31; v = We1[d * 1024 + f * 32 + o]; }
        else if (c < 544) { int o = c - 512;            v = be1[f * 32 + o]; }
        else              { int o = c - 544;            v = root1[f * 32 + o]; }
        g_W1cat[idx] = v;
    }
    for (int idx = idx0; idx < H1 * N2CAT; idx += stride) {
        int f = idx / N2CAT, c = idx % N2CAT;
        float v;
        if (c < 1024)      { int d = c >> 6, o = c & 63; v = We2[d * 2048 + f * 64 + o]; }
        else if (c < 1088) { int o = c - 1024;           v = be2[f * 64 + o]; }
        else               { int o = c - 1088;           v = root2[f * 64 + o]; }
        g_W2cat[idx] = v;
    }
    for (int idx = idx0; idx < FAA * N3CAT; idx += stride) {
        int f = idx / N3CAT, c = idx % N3CAT;
        float v = 0.f;
        if (f < 159) {
            if (c < 384) { int k = c >> 7, g = c & 127; v = ainit[(k * 159 + f) * 128 + g]; }
            else {
                int j = c - 384; int t = j / 384; int r = j - t * 384;
                int k = r >> 7, g = r & 127;
                v = aroot[((t * 3 + k) * 159 + f) * 128 + g];
            }
        }
        g_W3cat[idx] = v;
    }
}

__global__ void prep_csr(const int* __restrict__ aei) {
    if (blockIdx.x != 0 || threadIdx.x != 0) return;
    int deg[MAMN]; float dinv[MAMN]; int cur[MAMN];
    for (int m = 0; m < MAMN; m++) deg[m] = 0;
    for (int e = 0; e < EAED; e++) deg[aei[EAED + e]]++;
    for (int m = 0; m < MAMN; m++) dinv[m] = deg[m] > 0 ? 1.0f / sqrtf((float)deg[m]) : 0.0f;
    int off = 0;
    for (int m = 0; m < MAMN; m++) { g_off[m] = off; cur[m] = off; off += deg[m]; }
    g_off[MAMN] = off;
    for (int e = 0; e < EAED; e++) {
        int s = aei[e], d = aei[EAED + e];
        int slot = cur[d]++;
        g_csrc[slot] = s;
        g_cnorm[slot] = dinv[s] * dinv[d];
    }
}

// ---------------- f32x2 GEMM: 128x128 tile, 256 threads, 8x8 microtile ----------------
// CONV mode: cols < rootStart -> fp16 table Ch (row stride rootStart);
//            cols in [rootStart, N) -> hbuf fp32 (+bias).
template <bool RELU_A, bool CONV>
__global__ __launch_bounds__(256, 2)
void gemm_x2_kernel(const float* __restrict__ A, const float* __restrict__ B,
                    float* __restrict__ Cf, __half* __restrict__ Ch,
                    int M, int N, int K,
                    int rootStart, float* __restrict__ hbuf, int HW,
                    const float* __restrict__ bias) {
    __shared__ float As[32][128];
    __shared__ float Bs[32][128];
    int bm = blockIdx.y * 128, bn = blockIdx.x * 128;
    int tid = threadIdx.x;
    int ty = tid >> 4, tx = tid & 15;
    unsigned long long acc[8][4];
#pragma unroll
    for (int i = 0; i < 8; i++)
#pragma unroll
        for (int j = 0; j < 4; j++) acc[i][j] = 0ull;

    for (int k0 = 0; k0 < K; k0 += 32) {
#pragma unroll
        for (int j = 0; j < 4; j++) {
            int f4 = tid + j * 256;
            int r = f4 >> 3, cq = (f4 & 7) * 4;
            int gr = bm + r;
            float4 v = make_float4(0.f, 0.f, 0.f, 0.f);
            if (gr < M) {
                v = *(const float4*)(A + (size_t)gr * K + k0 + cq);
                if (RELU_A) {
                    v.x = fmaxf(v.x, 0.f); v.y = fmaxf(v.y, 0.f);
                    v.z = fmaxf(v.z, 0.f); v.w = fmaxf(v.w, 0.f);
                }
            }
            As[cq + 0][r] = v.x; As[cq + 1][r] = v.y;
            As[cq + 2][r] = v.z; As[cq + 3][r] = v.w;
        }
#pragma unroll
        for (int j = 0; j < 4; j++) {
            int f4 = tid + j * 256;
            int r = f4 >> 5, c4 = (f4 & 31) * 4;
            int gc = bn + c4;
            float4 v = make_float4(0.f, 0.f, 0.f, 0.f);
            if (gc < N) v = *(const float4*)(B + (size_t)(k0 + r) * N + gc);
            *(float4*)&Bs[r][c4] = v;
        }
        __syncthreads();
#pragma unroll
        for (int kk = 0; kk < 32; kk++) {
            float4 av0 = *(const float4*)&As[kk][ty * 8];
            float4 av1 = *(const float4*)&As[kk][ty * 8 + 4];
            ulonglong2 bv0 = *(const ulonglong2*)&Bs[kk][tx * 8];
            ulonglong2 bv1 = *(const ulonglong2*)&Bs[kk][tx * 8 + 4];
            unsigned long long a2[8];
            a2[0] = pk2(av0.x); a2[1] = pk2(av0.y); a2[2] = pk2(av0.z); a2[3] = pk2(av0.w);
            a2[4] = pk2(av1.x); a2[5] = pk2(av1.y); a2[6] = pk2(av1.z); a2[7] = pk2(av1.w);
            unsigned long long bb[4] = {bv0.x, bv0.y, bv1.x, bv1.y};
#pragma unroll
            for (int i = 0; i < 8; i++) {
                FMA2(acc[i][0], a2[i], bb[0]);
                FMA2(acc[i][1], a2[i], bb[1]);
                FMA2(acc[i][2], a2[i], bb[2]);
                FMA2(acc[i][3], a2[i], bb[3]);
            }
        }
        __syncthreads();
    }
#pragma unroll
    for (int i = 0; i < 8; i++) {
        int gr = bm + ty * 8 + i;
        if (gr >= M) continue;
#pragma unroll
        for (int h = 0; h < 2; h++) {
            int c0 = bn + tx * 8 + h * 4;
            float2 p0 = unpk2(acc[i][2 * h]);
            float2 p1 = unpk2(acc[i][2 * h + 1]);
            if (CONV) {
                if (c0 < rootStart) {
                    __half2 h0 = __floats2half2_rn(p0.x, p0.y);
                    __half2 h1 = __floats2half2_rn(p1.x, p1.y);
                    uint2 u;
                    u.x = *(unsigned*)&h0; u.y = *(unsigned*)&h1;
                    *(uint2*)(Ch + (size_t)gr * rootStart + c0) = u;
                } else if (c0 < N) {
                    int idx = c0 - rootStart;
                    float4 v = make_float4(p0.x + bias[idx], p0.y + bias[idx + 1],
                                           p1.x + bias[idx + 2], p1.y + bias[idx + 3]);
                    *(float4*)(hbuf + (size_t)gr * HW + idx) = v;
                }
            } else {
                if (c0 < N) {
                    float4 v = make_float4(p0.x, p0.y, p1.x, p1.y);
                    *(float4*)(Cf + (size_t)gr * N + c0) = v;
                }
            }
        }
    }
}

// ---------------- edge kernels (warp per edge, fp16 tables) ----------------
__global__ void edge1_kernel(const int* __restrict__ ei, const float* __restrict__ ea) {
    int e = (blockIdx.x * blockDim.x + threadIdx.x) >> 5;
    int lane = threadIdx.x & 31;
    if (e >= NEDGE) return;
    int src = ei[e], dst = ei[NEDGE + e];
    float av = (lane < 16) ? ea[e * 16 + lane] : 0.f;
    const __half* trow = g_C1h + (size_t)src * E1C;
    float acc = __half2float(trow[512 + lane]);   // b_e1 slice
#pragma unroll
    for (int d = 0; d < 16; d++) {
        float ed = __shfl_sync(0xffffffffu, av, d);
        acc += ed * __half2float(trow[d * 32 + lane]);
    }
    atomicAdd(g_h1 + (size_t)dst * H1 + lane, acc);
}
__global__ void edge2_kernel(const int* __restrict__ ei, const float* __restrict__ ea) {
    int e = (blockIdx.x * blockDim.x + threadIdx.x) >> 5;
    int lane = threadIdx.x & 31;
    if (e >= NEDGE) return;
    int src = ei[e], dst = ei[NEDGE + e];
    float av = (lane < 16) ? ea[e * 16 + lane] : 0.f;
    const __half* trow = g_C2h + (size_t)src * E2C;
    float acc0 = __half2float(trow[1024 + lane]);
    float acc1 = __half2float(trow[1056 + lane]);
#pragma unroll
    for (int d = 0; d < 16; d++) {
        float ed = __shfl_sync(0xffffffffu, av, d);
        acc0 += ed * __half2float(trow[d * 64 + lane]);
        acc1 += ed * __half2float(trow[d * 64 + 32 + lane]);
    }
    atomicAdd(g_h2 + (size_t)dst * H2 + lane, acc0);
    atomicAdd(g_h2 + (size_t)dst * H2 + 32 + lane, acc1);
}

// ---------------- attention readout (relu(h2) fused in) ----------------
__global__ void readout_kernel(const float* __restrict__ aaf, const int* __restrict__ labels,
                               const float* __restrict__ Wa, const float* __restrict__ ba) {
    __shared__ float lg[NPG];
    __shared__ float aas[MAMN * H2];
    __shared__ float red[256];
    __shared__ float was[H2];
    int b = blockIdx.x, tid = threadIdx.x;
    const float* Hrow = g_h2 + (size_t)b * NPG * H2;
    if (tid < H2) was[tid] = Wa[tid];
    __syncthreads();
    float lmax = -1e30f;
    for (int i = tid; i < NPG; i += 256) {
        float s = ba[0];
        const float* hr = Hrow + (size_t)i * H2;
        for (int o = 0; o < H2; o++) s += fmaxf(hr[o], 0.f) * was[o];
        lg[i] = s;
        lmax = fmaxf(lmax, s);
    }
    red[tid] = lmax; __syncthreads();
    for (int s = 128; s > 0; s >>= 1) { if (tid < s) red[tid] = fmaxf(red[tid], red[tid + s]); __syncthreads(); }
    float mx = red[0]; __syncthreads();
    float lsum = 0.f;
    for (int i = tid; i < NPG; i += 256) { float e = expf(lg[i] - mx); lg[i] = e; lsum += e; }
    red[tid] = lsum; __syncthreads();
    for (int s = 128; s > 0; s >>= 1) { if (tid < s) red[tid] += red[tid + s]; __syncthreads(); }
    float inv = 1.f / red[0];
    for (int i = tid; i < MAMN * H2; i += 256) aas[i] = 0.f;
    __syncthreads();
    int warp = tid >> 5, lane = tid & 31;
    for (int i = warp; i < NPG; i += 8) {
        float w = lg[i] * inv;
        int m = labels[b * NPG + i];
        const float* hr = Hrow + (size_t)i * H2;
        atomicAdd(&aas[m * H2 + lane], w * fmaxf(hr[lane], 0.f));
        atomicAdd(&aas[m * H2 + 32 + lane], w * fmaxf(hr[32 + lane], 0.f));
    }
    __syncthreads();
    for (int idx = tid; idx < MAMN * FAA; idx += 256) {
        int m = idx / FAA, c = idx % FAA;
        float v;
        if (c < H2)       v = aas[m * H2 + c];
        else if (c < 159) v = aaf[((size_t)b * MAMN + m) * AAFD + (c - H2)];
        else              v = 0.f;
        g_haa[((size_t)b * MAMN + m) * FAA + c] = v;
    }
}

// ---------------- ARMA: one block per (graph, stack); 512 threads ----------------
__global__ __launch_bounds__(512)
void arma_kernel(const float* __restrict__ arma_w, const float* __restrict__ arma_bias) {
    __shared__ float buf[MAMN * GDIM];
    __shared__ float Ws[16 * GDIM];
    __shared__ int   s_off[MAMN + 1];
    __shared__ int   s_src[EAED];
    __shared__ float s_norm[EAED];
    int b = blockIdx.x / KST, k = blockIdx.x % KST;
    int tid = threadIdx.x;
    int g = tid & 127, mh = tid >> 7;
    if (tid < MAMN + 1) s_off[tid] = g_off[tid];
    if (tid < EAED) { s_src[tid] = g_csrc[tid]; s_norm[tid] = g_cnorm[tid]; }
    const float* Cb = g_C3 + (size_t)(b * MAMN) * N3CAT;
#pragma unroll
    for (int r = 0; r < 13; r++) {
        int m = mh + 4 * r;
        if (m < MAMN) buf[m * GDIM + g] = Cb[(size_t)m * N3CAT + k * GDIM + g];
    }
    __syncthreads();
    for (int t = 0; t < TLAY; t++) {
        if (t > 0) {
            const float* Wg = arma_w + (size_t)((t - 1) * KST + k) * GDIM * GDIM;
            float acc[13];
#pragma unroll
            for (int r = 0; r < 13; r++) acc[r] = 0.f;
            for (int p0 = 0; p0 < GDIM; p0 += 16) {
                for (int j = tid; j < 16 * GDIM; j += 512) Ws[j] = Wg[(size_t)p0 * GDIM + j];
                __syncthreads();
#pragma unroll
                for (int pp = 0; pp < 16; pp++) {
                    float w = Ws[pp * GDIM + g];
#pragma unroll
                    for (int r = 0; r < 13; r++) {
                        int m = mh + 4 * r;
                        if (m < MAMN) acc[r] += buf[m * GDIM + (p0 + pp)] * w;
                    }
                }
                __syncthreads();
            }
#pragma unroll
            for (int r = 0; r < 13; r++) {
                int m = mh + 4 * r;
                if (m < MAMN) buf[m * GDIM + g] = acc[r];
            }
            __syncthreads();
        }
        float nv[13];
        float bias = arma_bias[(t * KST + k) * GDIM + g];
#pragma unroll
        for (int r = 0; r < 13; r++) {
            int m = mh + 4 * r;
            if (m < MAMN) {
                float s = 0.f;
                for (int j = s_off[m]; j < s_off[m + 1]; j++)
                    s += s_norm[j] * buf[s_src[j] * GDIM + g];
                float v = s + Cb[(size_t)m * N3CAT + 384 + (t * KST + k) * GDIM + g] + bias;
                nv[r] = fmaxf(v, 0.f);
            }
        }
        __syncthreads();
#pragma unroll
        for (int r = 0; r < 13; r++) {
            int m = mh + 4 * r;
            if (m < MAMN) buf[m * GDIM + g] = nv[r];
        }
        __syncthreads();
    }
#pragma unroll
    for (int r = 0; r < 13; r++) {
        int m = mh + 4 * r;
        if (m < MAMN)
            g_ao[((size_t)(b * KST + k) * MAMN + m) * GDIM + g] = buf[m * GDIM + g];
    }
}

// ---------------- final head ----------------
__global__ void final_kernel(const float* __restrict__ Waa, const float* __restrict__ baa,
                             const float* __restrict__ W1, const float* __restrict__ b1,
                             const float* __restrict__ W2, const float* __restrict__ b2,
                             const float* __restrict__ W3, const float* __restrict__ b3,
                             const float* __restrict__ W4, const float* __restrict__ b4,
                             float* __restrict__ out) {
    __shared__ float gs[MAMN * 132];
    __shared__ float at[MAMN];
    __shared__ float ps[128], p1[64], p2[32], p3[16];
    int b = blockIdx.x, tid = threadIdx.x; // 128 threads
    const float* A = g_ao + (size_t)b * KST * MAMN * GDIM;
    for (int idx = tid; idx < MAMN * GDIM; idx += 128) {
        int m = idx >> 7, g = idx & 127;
        float v = (A[m * GDIM + g] + A[MAMN * GDIM + m * GDIM + g] +
                   A[2 * MAMN * GDIM + m * GDIM + g]) * (1.f / 3.f);
        gs[m * 132 + g] = v;
    }
    __syncthreads();
    if (tid < MAMN) {
        float s = baa[0];
        for (int g = 0; g < GDIM; g++) s += gs[tid * 132 + g] * Waa[g];
        at[tid] = s;
    }
    __syncthreads();
    if (tid == 0) {
        float mx = -1e30f;
        for (int m = 0; m < MAMN; m++) mx = fmaxf(mx, at[m]);
        float tot = 0.f;
        for (int m = 0; m < MAMN; m++) { float e = expf(at[m] - mx); at[m] = e; tot += e; }
        float inv = 1.f / tot;
        for (int m = 0; m < MAMN; m++) at[m] *= inv;
    }
    __syncthreads();
    { float s = 0.f; for (int m = 0; m < MAMN; m++) s += at[m] * gs[m * 132 + tid]; ps[tid] = s; }
    __syncthreads();
    if (tid < 64) { float s = b1[tid]; for (int i = 0; i < 128; i++) s += ps[i] * W1[i * 64 + tid]; p1[tid] = fmaxf(s, 0.f); }
    __syncthreads();
    if (tid < 32) { float s = b2[tid]; for (int i = 0; i < 64; i++) s += p1[i] * W2[i * 32 + tid]; p2[tid] = fmaxf(s, 0.f); }
    __syncthreads();
    if (tid < 16) { float s = b3[tid]; for (int i = 0; i < 32; i++) s += p2[i] * W3[i * 16 + tid]; p3[tid] = fmaxf(s, 0.f); }
    __syncthreads();
    if (tid == 0) { float s = b4[0]; for (int i = 0; i < 16; i++) s += p3[i] * W4[i]; out[b] = s; }
}

// ---------------- launch ----------------
extern "C" void kernel_launch(void* const* d_in, const int* in_sizes, int n_in,
                              void* d_out, int out_size) {
    const float* x         = (const float*)d_in[0];
    const float* edge_attr = (const float*)d_in[1];
    const float* aaf       = (const float*)d_in[2];
    const int*   ei        = (const int*)d_in[3];
    const int*   labels    = (const int*)d_in[4];
    const int*   aei       = (const int*)d_in[5];
    const float* We1   = (const float*)d_in[6];
    const float* be1   = (const float*)d_in[7];
    const float* root1 = (const float*)d_in[8];
    const float* bias1 = (const float*)d_in[9];
    const float* We2   = (const float*)d_in[10];
    const float* be2   = (const float*)d_in[11];
    const float* root2 = (const float*)d_in[12];
    const float* bias2 = (const float*)d_in[13];
    const float* WaAtom = (const float*)d_in[14];
    const float* baAtom = (const float*)d_in[15];
    const float* armaw  = (const float*)d_in[17];
    const float* abias  = (const float*)d_in[19];
    const float* Waa    = (const float*)d_in[20];
    const float* baa    = (const float*)d_in[21];
    const float* W1 = (const float*)d_in[22];
    const float* b1 = (const float*)d_in[23];
    const float* W2 = (const float*)d_in[24];
    const float* b2 = (const float*)d_in[25];
    const float* W3 = (const float*)d_in[26];
    const float* b3 = (const float*)d_in[27];
    const float* W4 = (const float*)d_in[28];
    const float* b4 = (const float*)d_in[29];
    float* out = (float*)d_out;

    void *pC1h, *pC2h, *pC3, *ph1, *ph2, *phaa, *pW1c, *pW2c, *pW3c;
    cudaGetSymbolAddress(&pC1h, g_C1h);
    cudaGetSymbolAddress(&pC2h, g_C2h);
    cudaGetSymbolAddress(&pC3, g_C3);
    cudaGetSymbolAddress(&ph1, g_h1);
    cudaGetSymbolAddress(&ph2, g_h2);
    cudaGetSymbolAddress(&phaa, g_haa);
    cudaGetSymbolAddress(&pW1c, g_W1cat);
    cudaGetSymbolAddress(&pW2c, g_W2cat);
    cudaGetSymbolAddress(&pW3c, g_W3cat);

    prep_weights<<<256, 256>>>(We1, be1, root1, We2, be2, root2,
                               (const float*)d_in[16], (const float*)d_in[18]);
    prep_csr<<<1, 32>>>(aei);

    // conv1: fp16 edge table + fp32 h1 base (root+bias fused into epilogue)
    {
        dim3 grid((N1CAT + 127) / 128, (NATOM + 127) / 128);
        gemm_x2_kernel<false, true><<<grid, 256>>>(
            x, (const float*)pW1c, nullptr, (__half*)pC1h, NATOM, N1CAT, DIN,
            E1C, (float*)ph1, H1, bias1);
    }
    edge1_kernel<<<NEDGE / 8, 256>>>(ei, edge_attr);

    // conv2: A = relu(h1) fused into load
    {
        dim3 grid((N2CAT + 127) / 128, (NATOM + 127) / 128);
        gemm_x2_kernel<true, true><<<grid, 256>>>(
            (const float*)ph1, (const float*)pW2c, nullptr, (__half*)pC2h, NATOM, N2CAT, H1,
            E2C, (float*)ph2, H2, bias2);
    }
    edge2_kernel<<<NEDGE / 8, 256>>>(ei, edge_attr);

    // atom -> amino readout (relu(h2) fused into reads)
    readout_kernel<<<NB, 256>>>(aaf, labels, WaAtom, baAtom);

    // ARMA init + root precompute GEMM: [2500,160] @ [160,2688]
    {
        dim3 grid((N3CAT + 127) / 128, (NB * MAMN + 127) / 128);
        gemm_x2_kernel<false, false><<<grid, 256>>>(
            (const float*)phaa, (const float*)pW3c, (float*)pC3, nullptr,
            NB * MAMN, N3CAT, FAA, N3CAT, nullptr, 0, nullptr);
    }

    arma_kernel<<<NB * KST, 512>>>(armaw, abias);

    final_kernel<<<NB, 128>>>(Waa, baa, W1, b1, W2, b2, W3, b3, W4, b4, out);
}

// round 9
// speedup vs baseline: 1.5095x; 1.2242x over previous
#include <cuda_runtime.h>
#include <cuda_fp16.h>
#include <mma.h>
#include <math.h>
#include <stdint.h>

using namespace nvcuda;

// ---------------- problem constants ----------------
#define DIN   32
#define H1    32
#define H2    64
#define DE    16
#define NATOM 50000
#define NEDGE 100000
#define NB    50
#define NPG   1000
#define MAMN  50
#define AAFD  95
#define GDIM  128
#define KST   3
#define TLAY  6
#define EAED  98
#define FAA   160
#define N1CAT 576       // 512 edge-W + 32 b_e1 + 32 root1
#define E1C   544       // fp16 table width conv1 (edge + b_e)
#define N2CAT 1152      // 1024 edge-W + 64 b_e2 + 64 root2
#define E2C   1088      // fp16 table width conv2
#define N3CAT 2688      // 384 init (K*G) + 2304 root (T*K*G)

// ---------------- device scratch ----------------
__device__ __half g_C1h[(size_t)NATOM * E1C];   // 54.4 MB
__device__ __half g_C2h[(size_t)NATOM * E2C];   // 108.8 MB
__device__ float g_h1[NATOM * H1];
__device__ float g_h2[NATOM * H2];
__device__ float g_haa[NB * MAMN * FAA];
__device__ float g_C3[NB * MAMN * N3CAT];
__device__ float g_ao[NB * KST * MAMN * GDIM];
__device__ __half g_W1h[DIN * N1CAT];
__device__ __half g_W2h[H1 * N2CAT];
__device__ __half g_W3h[FAA * N3CAT];
__device__ int   g_off[MAMN + 1];
__device__ int   g_csrc[EAED];
__device__ float g_cnorm[EAED];

// ---------------- weight repack (to fp16) ----------------
__global__ void prep_weights(const float* __restrict__ We1, const float* __restrict__ be1,
                             const float* __restrict__ root1,
                             const float* __restrict__ We2, const float* __restrict__ be2,
                             const float* __restrict__ root2,
                             const float* __restrict__ ainit, const float* __restrict__ aroot) {
    int idx0 = blockIdx.x * blockDim.x + threadIdx.x;
    int stride = gridDim.x * blockDim.x;
    for (int idx = idx0; idx < DIN * N1CAT; idx += stride) {
        int f = idx / N1CAT, c = idx % N1CAT;
        float v;
        if (c < 512)      { int d = c >> 5, o = c & 31; v = We1[d * 1024 + f * 32 + o]; }
        else if (c < 544) { int o = c - 512;            v = be1[f * 32 + o]; }
        else              { int o = c - 544;            v = root1[f * 32 + o]; }
        g_W1h[idx] = __float2half(v);
    }
    for (int idx = idx0; idx < H1 * N2CAT; idx += stride) {
        int f = idx / N2CAT, c = idx % N2CAT;
        float v;
        if (c < 1024)      { int d = c >> 6, o = c & 63; v = We2[d * 2048 + f * 64 + o]; }
        else if (c < 1088) { int o = c - 1024;           v = be2[f * 64 + o]; }
        else               { int o = c - 1088;           v = root2[f * 64 + o]; }
        g_W2h[idx] = __float2half(v);
    }
    for (int idx = idx0; idx < FAA * N3CAT; idx += stride) {
        int f = idx / N3CAT, c = idx % N3CAT;
        float v = 0.f;
        if (f < 159) {
            if (c < 384) { int k = c >> 7, g = c & 127; v = ainit[(k * 159 + f) * 128 + g]; }
            else {
                int j = c - 384; int t = j / 384; int r = j - t * 384;
                int k = r >> 7, g = r & 127;
                v = aroot[((t * 3 + k) * 159 + f) * 128 + g];
            }
        }
        g_W3h[idx] = __float2half(v);
    }
}

__global__ void prep_csr(const int* __restrict__ aei) {
    if (blockIdx.x != 0 || threadIdx.x != 0) return;
    int deg[MAMN]; float dinv[MAMN]; int cur[MAMN];
    for (int m = 0; m < MAMN; m++) deg[m] = 0;
    for (int e = 0; e < EAED; e++) deg[aei[EAED + e]]++;
    for (int m = 0; m < MAMN; m++) dinv[m] = deg[m] > 0 ? 1.0f / sqrtf((float)deg[m]) : 0.0f;
    int off = 0;
    for (int m = 0; m < MAMN; m++) { g_off[m] = off; cur[m] = off; off += deg[m]; }
    g_off[MAMN] = off;
    for (int e = 0; e < EAED; e++) {
        int s = aei[e], d = aei[EAED + e];
        int slot = cur[d]++;
        g_csrc[slot] = s;
        g_cnorm[slot] = dinv[s] * dinv[d];
    }
}

// ---------------- HMMA GEMM: C[M,N] = A[M,K](fp32->fp16) @ B[K,N](fp16) ----------------
// Block tile 64(M) x 128(N), 256 threads = 8 warps in 2x4, warp tile 32x32 (2x2 wmma).
// K must be a multiple of 32; N a multiple of 32.
// CONV: cols < rootStart -> fp16 table Ch (row stride rootStart);
//       cols in [rootStart, N) -> hbuf fp32 (+bias). Boundaries multiple of 32.
template <bool RELU_A, bool CONV>
__global__ __launch_bounds__(256)
void gemm_wmma(const float* __restrict__ A, const __half* __restrict__ B,
               float* __restrict__ Cf, __half* __restrict__ Ch,
               int M, int N, int K,
               int rootStart, float* __restrict__ hbuf, int HW,
               const float* __restrict__ bias) {
    __shared__ __half Ah[64][40];     // lda 40 (mult of 8)
    __shared__ __half Bh[32][136];    // ldb 136
    __shared__ float  Ct[64][132];    // ldm 132 (mult of 4)
    int tid = threadIdx.x;
    int bm = blockIdx.y * 64, bn = blockIdx.x * 128;
    int warp = tid >> 5;
    int wm = warp >> 2, wn = warp & 3;

    wmma::fragment<wmma::accumulator, 16, 16, 16, float> acc[2][2];
#pragma unroll
    for (int i = 0; i < 2; i++)
#pragma unroll
        for (int j = 0; j < 2; j++) wmma::fill_fragment(acc[i][j], 0.0f);

    for (int k0 = 0; k0 < K; k0 += 32) {
        // A tile: 64x32 fp32 -> fp16 (relu fused)
#pragma unroll
        for (int it = 0; it < 2; it++) {
            int i = tid + it * 256;           // 512 quads
            int r = i >> 3, c4 = (i & 7) * 4;
            int gr = bm + r;
            float4 v = make_float4(0.f, 0.f, 0.f, 0.f);
            if (gr < M) v = *(const float4*)(A + (size_t)gr * K + k0 + c4);
            if (RELU_A) {
                v.x = fmaxf(v.x, 0.f); v.y = fmaxf(v.y, 0.f);
                v.z = fmaxf(v.z, 0.f); v.w = fmaxf(v.w, 0.f);
            }
            __half2 h0 = __floats2half2_rn(v.x, v.y);
            __half2 h1 = __floats2half2_rn(v.z, v.w);
            uint2 u; u.x = *(unsigned*)&h0; u.y = *(unsigned*)&h1;
            *(uint2*)&Ah[r][c4] = u;
        }
        // B tile: 32x128 fp16
#pragma unroll
        for (int it = 0; it < 2; it++) {
            int i = tid + it * 256;           // 512 chunks of 8 halves
            int r = i >> 4, c8 = (i & 15) * 8;
            int gc = bn + c8;
            uint4 u = make_uint4(0u, 0u, 0u, 0u);
            if (gc < N) u = *(const uint4*)(B + (size_t)(k0 + r) * N + gc);
            *(uint4*)&Bh[r][c8] = u;
        }
        __syncthreads();
#pragma unroll
        for (int kk = 0; kk < 2; kk++) {
            wmma::fragment<wmma::matrix_a, 16, 16, 16, __half, wmma::row_major> af[2];
            wmma::fragment<wmma::matrix_b, 16, 16, 16, __half, wmma::row_major> bf[2];
#pragma unroll
            for (int i = 0; i < 2; i++)
                wmma::load_matrix_sync(af[i], &Ah[wm * 32 + i * 16][kk * 16], 40);
#pragma unroll
            for (int j = 0; j < 2; j++)
                wmma::load_matrix_sync(bf[j], &Bh[kk * 16][wn * 32 + j * 16], 136);
#pragma unroll
            for (int i = 0; i < 2; i++)
#pragma unroll
                for (int j = 0; j < 2; j++)
                    wmma::mma_sync(acc[i][j], af[i], bf[j], acc[i][j]);
        }
        __syncthreads();
    }
    // stage accumulators to smem
#pragma unroll
    for (int i = 0; i < 2; i++)
#pragma unroll
        for (int j = 0; j < 2; j++)
            wmma::store_matrix_sync(&Ct[wm * 32 + i * 16][wn * 32 + j * 16],
                                    acc[i][j], 132, wmma::mem_row_major);
    __syncthreads();
    // copy out in column pairs (regions are 32-aligned, so pairs never straddle)
#pragma unroll
    for (int it = 0; it < 16; it++) {
        int i = tid + it * 256;               // 4096 pairs
        int r = i >> 6, c2 = (i & 63) * 2;
        int gr = bm + r, gc = bn + c2;
        if (gr >= M) continue;
        float v0 = Ct[r][c2], v1 = Ct[r][c2 + 1];
        if (CONV) {
            if (gc < rootStart) {
                __half2 h = __floats2half2_rn(v0, v1);
                *(__half2*)(Ch + (size_t)gr * rootStart + gc) = h;
            } else if (gc < N) {
                int idx = gc - rootStart;
                float2 o = make_float2(v0 + bias[idx], v1 + bias[idx + 1]);
                *(float2*)(hbuf + (size_t)gr * HW + idx) = o;
            }
        } else {
            if (gc < N) {
                float2 o = make_float2(v0, v1);
                *(float2*)(Cf + (size_t)gr * N + gc) = o;
            }
        }
    }
}

// ---------------- edge kernels (warp per edge, fp16 tables) ----------------
__global__ void edge1_kernel(const int* __restrict__ ei, const float* __restrict__ ea) {
    int e = (blockIdx.x * blockDim.x + threadIdx.x) >> 5;
    int lane = threadIdx.x & 31;
    if (e >= NEDGE) return;
    int src = ei[e], dst = ei[NEDGE + e];
    float av = (lane < 16) ? ea[e * 16 + lane] : 0.f;
    const __half* trow = g_C1h + (size_t)src * E1C;
    float acc = __half2float(trow[512 + lane]);   // b_e1 slice
#pragma unroll
    for (int d = 0; d < 16; d++) {
        float ed = __shfl_sync(0xffffffffu, av, d);
        acc += ed * __half2float(trow[d * 32 + lane]);
    }
    atomicAdd(g_h1 + (size_t)dst * H1 + lane, acc);
}
__global__ void edge2_kernel(const int* __restrict__ ei, const float* __restrict__ ea) {
    int e = (blockIdx.x * blockDim.x + threadIdx.x) >> 5;
    int lane = threadIdx.x & 31;
    if (e >= NEDGE) return;
    int src = ei[e], dst = ei[NEDGE + e];
    float av = (lane < 16) ? ea[e * 16 + lane] : 0.f;
    const __half* trow = g_C2h + (size_t)src * E2C;
    float acc0 = __half2float(trow[1024 + lane]);
    float acc1 = __half2float(trow[1056 + lane]);
#pragma unroll
    for (int d = 0; d < 16; d++) {
        float ed = __shfl_sync(0xffffffffu, av, d);
        acc0 += ed * __half2float(trow[d * 64 + lane]);
        acc1 += ed * __half2float(trow[d * 64 + 32 + lane]);
    }
    atomicAdd(g_h2 + (size_t)dst * H2 + lane, acc0);
    atomicAdd(g_h2 + (size_t)dst * H2 + 32 + lane, acc1);
}

// ---------------- attention readout (relu(h2) fused in) ----------------
__global__ void readout_kernel(const float* __restrict__ aaf, const int* __restrict__ labels,
                               const float* __restrict__ Wa, const float* __restrict__ ba) {
    __shared__ float lg[NPG];
    __shared__ float aas[MAMN * H2];
    __shared__ float red[256];
    __shared__ float was[H2];
    int b = blockIdx.x, tid = threadIdx.x;
    const float* Hrow = g_h2 + (size_t)b * NPG * H2;
    if (tid < H2) was[tid] = Wa[tid];
    __syncthreads();
    float lmax = -1e30f;
    for (int i = tid; i < NPG; i += 256) {
        float s = ba[0];
        const float* hr = Hrow + (size_t)i * H2;
        for (int o = 0; o < H2; o++) s += fmaxf(hr[o], 0.f) * was[o];
        lg[i] = s;
        lmax = fmaxf(lmax, s);
    }
    red[tid] = lmax; __syncthreads();
    for (int s = 128; s > 0; s >>= 1) { if (tid < s) red[tid] = fmaxf(red[tid], red[tid + s]); __syncthreads(); }
    float mx = red[0]; __syncthreads();
    float lsum = 0.f;
    for (int i = tid; i < NPG; i += 256) { float e = expf(lg[i] - mx); lg[i] = e; lsum += e; }
    red[tid] = lsum; __syncthreads();
    for (int s = 128; s > 0; s >>= 1) { if (tid < s) red[tid] += red[tid + s]; __syncthreads(); }
    float inv = 1.f / red[0];
    for (int i = tid; i < MAMN * H2; i += 256) aas[i] = 0.f;
    __syncthreads();
    int warp = tid >> 5, lane = tid & 31;
    for (int i = warp; i < NPG; i += 8) {
        float w = lg[i] * inv;
        int m = labels[b * NPG + i];
        const float* hr = Hrow + (size_t)i * H2;
        atomicAdd(&aas[m * H2 + lane], w * fmaxf(hr[lane], 0.f));
        atomicAdd(&aas[m * H2 + 32 + lane], w * fmaxf(hr[32 + lane], 0.f));
    }
    __syncthreads();
    for (int idx = tid; idx < MAMN * FAA; idx += 256) {
        int m = idx / FAA, c = idx % FAA;
        float v;
        if (c < H2)       v = aas[m * H2 + c];
        else if (c < 159) v = aaf[((size_t)b * MAMN + m) * AAFD + (c - H2)];
        else              v = 0.f;
        g_haa[((size_t)b * MAMN + m) * FAA + c] = v;
    }
}

// ---------------- ARMA: one block per (graph, stack); 512 threads ----------------
__global__ __launch_bounds__(512)
void arma_kernel(const float* __restrict__ arma_w, const float* __restrict__ arma_bias) {
    __shared__ float buf[MAMN * GDIM];
    __shared__ float Ws[16 * GDIM];
    __shared__ int   s_off[MAMN + 1];
    __shared__ int   s_src[EAED];
    __shared__ float s_norm[EAED];
    int b = blockIdx.x / KST, k = blockIdx.x % KST;
    int tid = threadIdx.x;
    int g = tid & 127, mh = tid >> 7;
    if (tid < MAMN + 1) s_off[tid] = g_off[tid];
    if (tid < EAED) { s_src[tid] = g_csrc[tid]; s_norm[tid] = g_cnorm[tid]; }
    const float* Cb = g_C3 + (size_t)(b * MAMN) * N3CAT;
#pragma unroll
    for (int r = 0; r < 13; r++) {
        int m = mh + 4 * r;
        if (m < MAMN) buf[m * GDIM + g] = Cb[(size_t)m * N3CAT + k * GDIM + g];
    }
    __syncthreads();
    for (int t = 0; t < TLAY; t++) {
        if (t > 0) {
            const float* Wg = arma_w + (size_t)((t - 1) * KST + k) * GDIM * GDIM;
            float acc[13];
#pragma unroll
            for (int r = 0; r < 13; r++) acc[r] = 0.f;
            for (int p0 = 0; p0 < GDIM; p0 += 16) {
                for (int j = tid; j < 16 * GDIM; j += 512) Ws[j] = Wg[(size_t)p0 * GDIM + j];
                __syncthreads();
#pragma unroll
                for (int pp = 0; pp < 16; pp++) {
                    float w = Ws[pp * GDIM + g];
#pragma unroll
                    for (int r = 0; r < 13; r++) {
                        int m = mh + 4 * r;
                        if (m < MAMN) acc[r] += buf[m * GDIM + (p0 + pp)] * w;
                    }
                }
                __syncthreads();
            }
#pragma unroll
            for (int r = 0; r < 13; r++) {
                int m = mh + 4 * r;
                if (m < MAMN) buf[m * GDIM + g] = acc[r];
            }
            __syncthreads();
        }
        float nv[13];
        float bias = arma_bias[(t * KST + k) * GDIM + g];
#pragma unroll
        for (int r = 0; r < 13; r++) {
            int m = mh + 4 * r;
            if (m < MAMN) {
                float s = 0.f;
                for (int j = s_off[m]; j < s_off[m + 1]; j++)
                    s += s_norm[j] * buf[s_src[j] * GDIM + g];
                float v = s + Cb[(size_t)m * N3CAT + 384 + (t * KST + k) * GDIM + g] + bias;
                nv[r] = fmaxf(v, 0.f);
            }
        }
        __syncthreads();
#pragma unroll
        for (int r = 0; r < 13; r++) {
            int m = mh + 4 * r;
            if (m < MAMN) buf[m * GDIM + g] = nv[r];
        }
        __syncthreads();
    }
#pragma unroll
    for (int r = 0; r < 13; r++) {
        int m = mh + 4 * r;
        if (m < MAMN)
            g_ao[((size_t)(b * KST + k) * MAMN + m) * GDIM + g] = buf[m * GDIM + g];
    }
}

// ---------------- final head ----------------
__global__ void final_kernel(const float* __restrict__ Waa, const float* __restrict__ baa,
                             const float* __restrict__ W1, const float* __restrict__ b1,
                             const float* __restrict__ W2, const float* __restrict__ b2,
                             const float* __restrict__ W3, const float* __restrict__ b3,
                             const float* __restrict__ W4, const float* __restrict__ b4,
                             float* __restrict__ out) {
    __shared__ float gs[MAMN * 132];
    __shared__ float at[MAMN];
    __shared__ float ps[128], p1[64], p2[32], p3[16];
    int b = blockIdx.x, tid = threadIdx.x; // 128 threads
    const float* A = g_ao + (size_t)b * KST * MAMN * GDIM;
    for (int idx = tid; idx < MAMN * GDIM; idx += 128) {
        int m = idx >> 7, g = idx & 127;
        float v = (A[m * GDIM + g] + A[MAMN * GDIM + m * GDIM + g] +
                   A[2 * MAMN * GDIM + m * GDIM + g]) * (1.f / 3.f);
        gs[m * 132 + g] = v;
    }
    __syncthreads();
    if (tid < MAMN) {
        float s = baa[0];
        for (int g = 0; g < GDIM; g++) s += gs[tid * 132 + g] * Waa[g];
        at[tid] = s;
    }
    __syncthreads();
    if (tid == 0) {
        float mx = -1e30f;
        for (int m = 0; m < MAMN; m++) mx = fmaxf(mx, at[m]);
        float tot = 0.f;
        for (int m = 0; m < MAMN; m++) { float e = expf(at[m] - mx); at[m] = e; tot += e; }
        float inv = 1.f / tot;
        for (int m = 0; m < MAMN; m++) at[m] *= inv;
    }
    __syncthreads();
    { float s = 0.f; for (int m = 0; m < MAMN; m++) s += at[m] * gs[m * 132 + tid]; ps[tid] = s; }
    __syncthreads();
    if (tid < 64) { float s = b1[tid]; for (int i = 0; i < 128; i++) s += ps[i] * W1[i * 64 + tid]; p1[tid] = fmaxf(s, 0.f); }
    __syncthreads();
    if (tid < 32) { float s = b2[tid]; for (int i = 0; i < 64; i++) s += p1[i] * W2[i * 32 + tid]; p2[tid] = fmaxf(s, 0.f); }
    __syncthreads();
    if (tid < 16) { float s = b3[tid]; for (int i = 0; i < 32; i++) s += p2[i] * W3[i * 16 + tid]; p3[tid] = fmaxf(s, 0.f); }
    __syncthreads();
    if (tid == 0) { float s = b4[0]; for (int i = 0; i < 16; i++) s += p3[i] * W4[i]; out[b] = s; }
}

// ---------------- launch ----------------
extern "C" void kernel_launch(void* const* d_in, const int* in_sizes, int n_in,
                              void* d_out, int out_size) {
    const float* x         = (const float*)d_in[0];
    const float* edge_attr = (const float*)d_in[1];
    const float* aaf       = (const float*)d_in[2];
    const int*   ei        = (const int*)d_in[3];
    const int*   labels    = (const int*)d_in[4];
    const int*   aei       = (const int*)d_in[5];
    const float* We1   = (const float*)d_in[6];
    const float* be1   = (const float*)d_in[7];
    const float* root1 = (const float*)d_in[8];
    const float* bias1 = (const float*)d_in[9];
    const float* We2   = (const float*)d_in[10];
    const float* be2   = (const float*)d_in[11];
    const float* root2 = (const float*)d_in[12];
    const float* bias2 = (const float*)d_in[13];
    const float* WaAtom = (const float*)d_in[14];
    const float* baAtom = (const float*)d_in[15];
    const float* armaw  = (const float*)d_in[17];
    const float* abias  = (const float*)d_in[19];
    const float* Waa    = (const float*)d_in[20];
    const float* baa    = (const float*)d_in[21];
    const float* W1 = (const float*)d_in[22];
    const float* b1 = (const float*)d_in[23];
    const float* W2 = (const float*)d_in[24];
    const float* b2 = (const float*)d_in[25];
    const float* W3 = (const float*)d_in[26];
    const float* b3 = (const float*)d_in[27];
    const float* W4 = (const float*)d_in[28];
    const float* b4 = (const float*)d_in[29];
    float* out = (float*)d_out;

    void *pC1h, *pC2h, *pC3, *ph1, *ph2, *phaa, *pW1h, *pW2h, *pW3h;
    cudaGetSymbolAddress(&pC1h, g_C1h);
    cudaGetSymbolAddress(&pC2h, g_C2h);
    cudaGetSymbolAddress(&pC3, g_C3);
    cudaGetSymbolAddress(&ph1, g_h1);
    cudaGetSymbolAddress(&ph2, g_h2);
    cudaGetSymbolAddress(&phaa, g_haa);
    cudaGetSymbolAddress(&pW1h, g_W1h);
    cudaGetSymbolAddress(&pW2h, g_W2h);
    cudaGetSymbolAddress(&pW3h, g_W3h);

    prep_weights<<<256, 256>>>(We1, be1, root1, We2, be2, root2,
                               (const float*)d_in[16], (const float*)d_in[18]);
    prep_csr<<<1, 32>>>(aei);

    // conv1: fp16 edge table + fp32 h1 base (root+bias fused into epilogue)
    {
        dim3 grid((N1CAT + 127) / 128, (NATOM + 63) / 64);
        gemm_wmma<false, true><<<grid, 256>>>(
            x, (const __half*)pW1h, nullptr, (__half*)pC1h, NATOM, N1CAT, DIN,
            E1C, (float*)ph1, H1, bias1);
    }
    edge1_kernel<<<NEDGE / 8, 256>>>(ei, edge_attr);

    // conv2: A = relu(h1) fused into load
    {
        dim3 grid((N2CAT + 127) / 128, (NATOM + 63) / 64);
        gemm_wmma<true, true><<<grid, 256>>>(
            (const float*)ph1, (const __half*)pW2h, nullptr, (__half*)pC2h, NATOM, N2CAT, H1,
            E2C, (float*)ph2, H2, bias2);
    }
    edge2_kernel<<<NEDGE / 8, 256>>>(ei, edge_attr);

    // atom -> amino readout (relu(h2) fused into reads)
    readout_kernel<<<NB, 256>>>(aaf, labels, WaAtom, baAtom);

    // ARMA init + root precompute GEMM: [2500,160] @ [160,2688]
    {
        dim3 grid((N3CAT + 127) / 128, (NB * MAMN + 63) / 64);
        gemm_wmma<false, false><<<grid, 256>>>(
            (const float*)phaa, (const __half*)pW3h, (float*)pC3, nullptr,
            NB * MAMN, N3CAT, FAA, N3CAT, nullptr, 0, nullptr);
    }

    arma_kernel<<<NB * KST, 512>>>(armaw, abias);

    final_kernel<<<NB, 128>>>(Waa, baa, W1, b1, W2, b2, W3, b3, W4, b4, out);
}